// round 7
// baseline (speedup 1.0000x reference)
#include <cuda_runtime.h>
#include <cuda_fp16.h>
#include <cstdint>

// ---------------------------------------------------------------------------
// Problem constants
// ---------------------------------------------------------------------------
#define N_NODES 500000
#define S_SAMPLE 100000
#define EQCAP 8192
#define OUT_C 256
#define IN_C 256
#define M_TILE 64
#define NBLK ((S_SAMPLE + M_TILE - 1) / M_TILE)   // 1563
#define NZERO 2048
#define NTOT (NBLK + NZERO)                       // 3611

// libdevice accurate log (immune to fast-math logf substitution)
extern "C" __device__ float __nv_logf(float);

// ---------------------------------------------------------------------------
// Device scratch
// ---------------------------------------------------------------------------
__device__ unsigned g_keys[N_NODES];
__device__ unsigned char g_flag[N_NODES];
__device__ int g_sel[S_SAMPLE + M_TILE];
__device__ int g_eqList[EQCAP];
__device__ unsigned g_h16[65536];
__device__ unsigned g_c256[256];
__device__ unsigned g_P16;
__device__ int g_counters[4];
__device__ unsigned g_wh[32768];   // w as f16 pairs, [k][n] row-major
#define C_SEL 0
#define C_EQ 1
#define C_REM 2

// ---------------------------------------------------------------------------
// Threefry-2x32, partitionable: x0=0, x1=i, key=(0,42); draw = out0 ^ out1
// (validated exact, round 4)
// ---------------------------------------------------------------------------
__device__ __forceinline__ unsigned rotl32(unsigned x, int r) {
    return (x << r) | (x >> (32 - r));
}
__device__ __forceinline__ unsigned threefry_bits(unsigned i) {
    const unsigned ks0 = 0u, ks1 = 42u;
    const unsigned ks2 = 0x1BD11BDAu ^ ks0 ^ ks1;
    unsigned x0 = 0u + ks0;
    unsigned x1 = i + ks1;
#define TF_R4(a, b, c, d)                                   \
    x0 += x1; x1 = rotl32(x1, a); x1 ^= x0;                 \
    x0 += x1; x1 = rotl32(x1, b); x1 ^= x0;                 \
    x0 += x1; x1 = rotl32(x1, c); x1 ^= x0;                 \
    x0 += x1; x1 = rotl32(x1, d); x1 ^= x0;
    TF_R4(13, 15, 26, 6)  x0 += ks1; x1 += ks2 + 1u;
    TF_R4(17, 29, 16, 24) x0 += ks2; x1 += ks0 + 2u;
    TF_R4(13, 15, 26, 6)  x0 += ks0; x1 += ks1 + 3u;
    TF_R4(17, 29, 16, 24) x0 += ks1; x1 += ks2 + 4u;
    TF_R4(13, 15, 26, 6)  x0 += ks2; x1 += ks0 + 5u;
#undef TF_R4
    return x0 ^ x1;
}
__device__ __forceinline__ unsigned f2key(float f) {
    unsigned b = __float_as_uint(f);
    return (b & 0x80000000u) ? ~b : (b | 0x80000000u);
}

// ---------------------------------------------------------------------------
// prep: zero hists/counters + convert w to f16
// ---------------------------------------------------------------------------
__global__ void prep_kernel(const float* __restrict__ w) {
    int t = blockIdx.x * blockDim.x + threadIdx.x;   // 32768 threads
    g_h16[t] = 0;
    g_h16[t + 32768] = 0;
    if (t < 256) g_c256[t] = 0;
    if (t < 4) g_counters[t] = 0;
    float2 v = ((const float2*)w)[t];
    __half2 h = __floats2half2_rn(v.x, v.y);
    g_wh[t] = *(unsigned*)&h;
}

// ---------------------------------------------------------------------------
// score: keys + 16-bit histogram (+ shared-aggregated coarse 256)
// ---------------------------------------------------------------------------
__global__ void score_kernel(const float* __restrict__ imp) {
    __shared__ unsigned sh[256];
    int tid = threadIdx.x;
    sh[tid] = 0;
    __syncthreads();
    int i = blockIdx.x * blockDim.x + tid;
    if (i < N_NODES) {
        unsigned bits = threefry_bits((unsigned)i);
        float f = __uint_as_float((bits >> 9) | 0x3F800000u) - 1.0f;
        float u = f + 1.17549435e-38f;
        float g = -__nv_logf(-__nv_logf(u));
        unsigned k = f2key(__nv_logf(imp[i]) + g);
        g_keys[i] = k;
        atomicAdd(&sh[k >> 24], 1u);
        atomicAdd(&g_h16[k >> 16], 1u);
    }
    __syncthreads();
    if (sh[tid]) atomicAdd(&g_c256[tid], sh[tid]);
}

// ---------------------------------------------------------------------------
// pick16: one block; exact top-16-bit threshold via two suffix scans
// ---------------------------------------------------------------------------
__global__ void pick16_kernel() {
    __shared__ unsigned suf[256];
    __shared__ unsigned sb0, sneed;
    int t = threadIdx.x;
    suf[t] = g_c256[t];
    __syncthreads();
#pragma unroll
    for (int off = 1; off < 256; off <<= 1) {
        unsigned v = (t + off < 256) ? suf[t + off] : 0u;
        __syncthreads();
        suf[t] += v;
        __syncthreads();
    }
    {
        unsigned need = S_SAMPLE;
        unsigned above = (t < 255) ? suf[t + 1] : 0u;
        if (suf[t] >= need && above < need) { sb0 = (unsigned)t; sneed = need - above; }
    }
    __syncthreads();
    unsigned b0 = sb0, need2 = sneed;
    suf[t] = g_h16[b0 * 256 + t];
    __syncthreads();
#pragma unroll
    for (int off = 1; off < 256; off <<= 1) {
        unsigned v = (t + off < 256) ? suf[t + off] : 0u;
        __syncthreads();
        suf[t] += v;
        __syncthreads();
    }
    {
        unsigned above = (t < 255) ? suf[t + 1] : 0u;
        if (suf[t] >= need2 && above < need2) {
            g_P16 = (b0 << 8) | (unsigned)t;
            g_counters[C_REM] = (int)(need2 - above);
        }
    }
}

// ---------------------------------------------------------------------------
// flag: one full scan; >P16 selected, ==P16 to tiny eq list
// ---------------------------------------------------------------------------
__global__ void flag_kernel() {
    int i = blockIdx.x * blockDim.x + threadIdx.x;
    if (i >= N_NODES) return;
    unsigned p = g_keys[i] >> 16;
    unsigned P = g_P16;
    if (p > P) {
        g_flag[i] = 1;
        int q = atomicAdd(&g_counters[C_SEL], 1);
        if (q < S_SAMPLE + M_TILE) g_sel[q] = i;
    } else if (p == P) {
        g_flag[i] = 0;
        int e = atomicAdd(&g_counters[C_EQ], 1);
        if (e < EQCAP) g_eqList[e] = i;
    } else {
        g_flag[i] = 0;
    }
}

// eq resolution: top-d among equal-prefix keys by (key desc, index asc)
__global__ void eq_pick_kernel() {
    int n = g_counters[C_EQ];
    if (n > EQCAP) n = EQCAP;
    int d = g_counters[C_REM];
    for (int t = threadIdx.x; t < n; t += blockDim.x) {
        int idx_i = g_eqList[t];
        unsigned key_i = g_keys[idx_i];
        int rank = 0;
        for (int j = 0; j < n; j++) {
            int idx_j = g_eqList[j];
            unsigned key_j = g_keys[idx_j];
            rank += (key_j > key_i) || (key_j == key_i && idx_j < idx_i);
        }
        if (rank < d) {
            g_flag[idx_i] = 1;   // zero-role must skip (gemm writes it)
            int q = atomicAdd(&g_counters[C_SEL], 1);
            if (q < S_SAMPLE + M_TILE) g_sel[q] = idx_i;
        }
    }
}

// ---------------------------------------------------------------------------
// fused GEMM + zero. Roles interleaved by blockIdx for overlap:
//   bid < 2*NBLK: even -> gemm(bid/2), odd -> zero(bid/2)
//   else         : zero(NBLK + bid - 2*NBLK)
// GEMM: M=64 gathered rows x N=256, K=256. A full-K resident in smem (f16),
// B in 32-k chunks from prepped w. 8 warps, each 2x8 m16n8k16 HMMA tiles.
// ---------------------------------------------------------------------------
#define A_STRIDE 264   // halves; 528B row stride
#define B_STRIDE 264
#define AS_BYTES (M_TILE * A_STRIDE * 2)          // 33792
#define BS_BYTES (32 * B_STRIDE * 2)              // 16896
#define SMEM_DYN (AS_BYTES + BS_BYTES)            // 50688

__device__ __forceinline__ uint32_t smem_u32(const void* p) {
    uint32_t a;
    asm("{ .reg .u64 t; cvta.to.shared.u64 t, %1; cvt.u32.u64 %0, t; }"
        : "=r"(a) : "l"(p));
    return a;
}

__global__ void __launch_bounds__(256, 2) fused_kernel(
    const float* __restrict__ x, const float* __restrict__ bias,
    float* __restrict__ out) {
    extern __shared__ __align__(16) char dsm[];
    __shared__ int rows_s[M_TILE];

    int bid = blockIdx.x;
    int tid = threadIdx.x;
    int wid = tid >> 5;
    int lane = tid & 31;

    int gemm_id = -1, zero_id;
    if (bid < 2 * NBLK) {
        if ((bid & 1) == 0) gemm_id = bid >> 1;
        else zero_id = bid >> 1;
    } else {
        zero_id = NBLK + (bid - 2 * NBLK);
    }

    if (gemm_id < 0) {
        // ---- zero role: zero unselected rows ----
        int gw = zero_id * 8 + wid;
        float4 z = make_float4(0.f, 0.f, 0.f, 0.f);
        for (int row = gw; row < N_NODES; row += NZERO * 8) {
            if (!g_flag[row]) {
                float4* p = (float4*)(out + (size_t)row * OUT_C);
                p[lane] = z;
                p[lane + 32] = z;
            }
        }
        return;
    }

    // ---- gemm role ----
    __half* As = (__half*)dsm;
    __half* Bs = (__half*)(dsm + AS_BYTES);
    const uint32_t As_base = smem_u32(As);
    const uint32_t Bs_base = smem_u32(Bs);

    int r0 = gemm_id * M_TILE;
    if (tid < M_TILE) {
        int rr = r0 + tid;
        rows_s[tid] = g_sel[(rr < S_SAMPLE) ? rr : r0];
    }
    __syncthreads();

    // A: full-K gather, f32 -> f16 (4 threads per row, 16 float4 each)
    {
        int row = tid >> 2;
        int quarter = tid & 3;
        const float4* src = (const float4*)(x + (size_t)rows_s[row] * IN_C);
        __half* dstrow = As + row * A_STRIDE;
#pragma unroll
        for (int j = 0; j < 16; j++) {
            int c4 = quarter + 4 * j;
            float4 v = src[c4];
            __half2 h0 = __floats2half2_rn(v.x, v.y);
            __half2 h1 = __floats2half2_rn(v.z, v.w);
            uint2 pk;
            pk.x = *(unsigned*)&h0;
            pk.y = *(unsigned*)&h1;
            *(uint2*)(dstrow + c4 * 4) = pk;
        }
    }

    int m_half = wid & 1;
    int n_quad = wid >> 1;
    float acc[2][8][4];
#pragma unroll
    for (int mt = 0; mt < 2; mt++)
#pragma unroll
        for (int nt = 0; nt < 8; nt++)
#pragma unroll
            for (int q = 0; q < 4; q++) acc[mt][nt][q] = 0.f;

    int b_krow = tid >> 3;
    int b_seg = (tid & 7) * 32;

    for (int kc = 0; kc < 8; kc++) {
        __syncthreads();   // also covers initial A-store visibility
        // B chunk: 32 k-rows x 256 halves (L2-hot)
        {
            const uint4* src = (const uint4*)&g_wh[(kc * 32 + b_krow) * 128 + b_seg / 2];
            uint4* dst = (uint4*)&Bs[b_krow * B_STRIDE + b_seg];
            dst[0] = src[0];
            dst[1] = src[1];
            dst[2] = src[2];
            dst[3] = src[3];
        }
        __syncthreads();

#pragma unroll
        for (int ks = 0; ks < 2; ks++) {
            uint32_t af[2][4];
#pragma unroll
            for (int mt = 0; mt < 2; mt++) {
                int row = m_half * 32 + mt * 16 + (lane & 15);
                int col = kc * 32 + ks * 16 + (lane >> 4) * 8;
                uint32_t addr = As_base + (row * A_STRIDE + col) * 2;
                asm volatile(
                    "ldmatrix.sync.aligned.m8n8.x4.shared.b16 {%0,%1,%2,%3}, [%4];"
                    : "=r"(af[mt][0]), "=r"(af[mt][1]),
                      "=r"(af[mt][2]), "=r"(af[mt][3]) : "r"(addr));
            }
            uint32_t bf[8][2];
#pragma unroll
            for (int nt = 0; nt < 8; nt++) {
                int krow = ks * 16 + (lane & 15);
                int ncol = n_quad * 64 + nt * 8;
                uint32_t addr = Bs_base + (krow * B_STRIDE + ncol) * 2;
                asm volatile(
                    "ldmatrix.sync.aligned.m8n8.x2.trans.shared.b16 {%0,%1}, [%2];"
                    : "=r"(bf[nt][0]), "=r"(bf[nt][1]) : "r"(addr));
            }
#pragma unroll
            for (int mt = 0; mt < 2; mt++)
#pragma unroll
                for (int nt = 0; nt < 8; nt++) {
                    asm volatile(
                        "mma.sync.aligned.m16n8k16.row.col.f32.f16.f16.f32 "
                        "{%0,%1,%2,%3}, {%4,%5,%6,%7}, {%8,%9}, {%0,%1,%2,%3};"
                        : "+f"(acc[mt][nt][0]), "+f"(acc[mt][nt][1]),
                          "+f"(acc[mt][nt][2]), "+f"(acc[mt][nt][3])
                        : "r"(af[mt][0]), "r"(af[mt][1]),
                          "r"(af[mt][2]), "r"(af[mt][3]),
                          "r"(bf[nt][0]), "r"(bf[nt][1]));
                }
        }
    }

    // epilogue: (acc + bias) * 5, scatter
    const float scale = 5.0f;
    int qr = lane >> 2;
    int qc = (lane & 3) * 2;
#pragma unroll
    for (int mt = 0; mt < 2; mt++) {
        int lrow_lo = m_half * 32 + mt * 16 + qr;
        int g_lo = rows_s[lrow_lo];
        int g_hi = rows_s[lrow_lo + 8];
        float* row_lo = out + (size_t)g_lo * OUT_C;
        float* row_hi = out + (size_t)g_hi * OUT_C;
#pragma unroll
        for (int nt = 0; nt < 8; nt++) {
            int col = n_quad * 64 + nt * 8 + qc;
            float b0 = bias[col], b1 = bias[col + 1];
            *(float2*)(row_lo + col) = make_float2(
                (acc[mt][nt][0] + b0) * scale, (acc[mt][nt][1] + b1) * scale);
            *(float2*)(row_hi + col) = make_float2(
                (acc[mt][nt][2] + b0) * scale, (acc[mt][nt][3] + b1) * scale);
        }
    }
}

// ---------------------------------------------------------------------------
// Launch
// ---------------------------------------------------------------------------
extern "C" void kernel_launch(void* const* d_in, const int* in_sizes, int n_in,
                              void* d_out, int out_size) {
    const float* x = nullptr;
    const float* w = nullptr;
    const float* bias = nullptr;
    const float* imp = nullptr;
    for (int i = 0; i < n_in; i++) {
        switch (in_sizes[i]) {
            case 128000000: x = (const float*)d_in[i]; break;
            case 65536:     w = (const float*)d_in[i]; break;
            case 256:       bias = (const float*)d_in[i]; break;
            case 500000:    imp = (const float*)d_in[i]; break;
            default: break;  // edge_index unused
        }
    }
    float* out = (float*)d_out;
    (void)out_size;

    cudaFuncSetAttribute(fused_kernel,
                         cudaFuncAttributeMaxDynamicSharedMemorySize, SMEM_DYN);

    prep_kernel<<<128, 256>>>(w);
    score_kernel<<<(N_NODES + 255) / 256, 256>>>(imp);
    pick16_kernel<<<1, 256>>>();
    flag_kernel<<<(N_NODES + 255) / 256, 256>>>();
    eq_pick_kernel<<<1, 256>>>();
    fused_kernel<<<NTOT, 256, SMEM_DYN>>>(x, bias, out);
}

// round 8
// speedup vs baseline: 29.7450x; 29.7450x over previous
#include <cuda_runtime.h>
#include <cuda_fp16.h>
#include <cstdint>

// ---------------------------------------------------------------------------
// Problem constants
// ---------------------------------------------------------------------------
#define N_NODES 500000
#define S_SAMPLE 100000
#define EQCAP 32768
#define OUT_C 256
#define IN_C 256
#define M_TILE 64
#define NBLK ((S_SAMPLE + M_TILE - 1) / M_TILE)   // 1563
#define NZERO 2048
#define NTOT (NBLK + NZERO)

// libdevice accurate log (immune to fast-math logf substitution)
extern "C" __device__ float __nv_logf(float);

// ---------------------------------------------------------------------------
// Device scratch
// ---------------------------------------------------------------------------
__device__ unsigned g_keys[N_NODES];
__device__ unsigned char g_flag[N_NODES];
__device__ int g_sel[S_SAMPLE + M_TILE];
__device__ int g_eqList[EQCAP];
__device__ unsigned g_h16[65536];
__device__ unsigned g_c256[256];
__device__ unsigned g_P16;
__device__ int g_counters[4];
__device__ unsigned g_wh[32768];   // w as f16 pairs, [k][n] row-major
#define C_SEL 0
#define C_EQ 1
#define C_REM 2

// ---------------------------------------------------------------------------
// Threefry-2x32, partitionable: x0=0, x1=i, key=(0,42); draw = out0 ^ out1
// (validated exact, round 4)
// ---------------------------------------------------------------------------
__device__ __forceinline__ unsigned rotl32(unsigned x, int r) {
    return (x << r) | (x >> (32 - r));
}
__device__ __forceinline__ unsigned threefry_bits(unsigned i) {
    const unsigned ks0 = 0u, ks1 = 42u;
    const unsigned ks2 = 0x1BD11BDAu ^ ks0 ^ ks1;
    unsigned x0 = 0u + ks0;
    unsigned x1 = i + ks1;
#define TF_R4(a, b, c, d)                                   \
    x0 += x1; x1 = rotl32(x1, a); x1 ^= x0;                 \
    x0 += x1; x1 = rotl32(x1, b); x1 ^= x0;                 \
    x0 += x1; x1 = rotl32(x1, c); x1 ^= x0;                 \
    x0 += x1; x1 = rotl32(x1, d); x1 ^= x0;
    TF_R4(13, 15, 26, 6)  x0 += ks1; x1 += ks2 + 1u;
    TF_R4(17, 29, 16, 24) x0 += ks2; x1 += ks0 + 2u;
    TF_R4(13, 15, 26, 6)  x0 += ks0; x1 += ks1 + 3u;
    TF_R4(17, 29, 16, 24) x0 += ks1; x1 += ks2 + 4u;
    TF_R4(13, 15, 26, 6)  x0 += ks2; x1 += ks0 + 5u;
#undef TF_R4
    return x0 ^ x1;
}
__device__ __forceinline__ unsigned f2key(float f) {
    unsigned b = __float_as_uint(f);
    return (b & 0x80000000u) ? ~b : (b | 0x80000000u);
}

// ---------------------------------------------------------------------------
// prep: zero hists/counters + convert w to f16
// ---------------------------------------------------------------------------
__global__ void prep_kernel(const float* __restrict__ w) {
    int t = blockIdx.x * blockDim.x + threadIdx.x;   // 32768 threads
    g_h16[t] = 0;
    g_h16[t + 32768] = 0;
    if (t < 256) g_c256[t] = 0;
    if (t < 4) g_counters[t] = 0;
    float2 v = ((const float2*)w)[t];
    __half2 h = __floats2half2_rn(v.x, v.y);
    g_wh[t] = *(unsigned*)&h;
}

// ---------------------------------------------------------------------------
// score: keys + 16-bit histogram (+ shared-aggregated coarse 256)
// ---------------------------------------------------------------------------
__global__ void score_kernel(const float* __restrict__ imp) {
    __shared__ unsigned sh[256];
    int tid = threadIdx.x;
    sh[tid] = 0;
    __syncthreads();
    int i = blockIdx.x * blockDim.x + tid;
    if (i < N_NODES) {
        unsigned bits = threefry_bits((unsigned)i);
        float f = __uint_as_float((bits >> 9) | 0x3F800000u) - 1.0f;
        float u = f + 1.17549435e-38f;
        float g = -__nv_logf(-__nv_logf(u));
        unsigned k = f2key(__nv_logf(imp[i]) + g);
        g_keys[i] = k;
        atomicAdd(&sh[k >> 24], 1u);
        atomicAdd(&g_h16[k >> 16], 1u);
    }
    __syncthreads();
    if (sh[tid]) atomicAdd(&g_c256[tid], sh[tid]);
}

// ---------------------------------------------------------------------------
// pick16: one block; exact top-16-bit threshold via two suffix scans
// ---------------------------------------------------------------------------
__global__ void pick16_kernel() {
    __shared__ unsigned suf[256];
    __shared__ unsigned sb0, sneed;
    int t = threadIdx.x;
    suf[t] = g_c256[t];
    __syncthreads();
#pragma unroll
    for (int off = 1; off < 256; off <<= 1) {
        unsigned v = (t + off < 256) ? suf[t + off] : 0u;
        __syncthreads();
        suf[t] += v;
        __syncthreads();
    }
    {
        unsigned need = S_SAMPLE;
        unsigned above = (t < 255) ? suf[t + 1] : 0u;
        if (suf[t] >= need && above < need) { sb0 = (unsigned)t; sneed = need - above; }
    }
    __syncthreads();
    unsigned b0 = sb0, need2 = sneed;
    suf[t] = g_h16[b0 * 256 + t];
    __syncthreads();
#pragma unroll
    for (int off = 1; off < 256; off <<= 1) {
        unsigned v = (t + off < 256) ? suf[t + off] : 0u;
        __syncthreads();
        suf[t] += v;
        __syncthreads();
    }
    {
        unsigned above = (t < 255) ? suf[t + 1] : 0u;
        if (suf[t] >= need2 && above < need2) {
            g_P16 = (b0 << 8) | (unsigned)t;
            g_counters[C_REM] = (int)(need2 - above);
        }
    }
}

// ---------------------------------------------------------------------------
// flag: one full scan; >P16 selected, ==P16 to eq list
// ---------------------------------------------------------------------------
__global__ void flag_kernel() {
    int i = blockIdx.x * blockDim.x + threadIdx.x;
    if (i >= N_NODES) return;
    unsigned p = g_keys[i] >> 16;
    unsigned P = g_P16;
    if (p > P) {
        g_flag[i] = 1;
        int q = atomicAdd(&g_counters[C_SEL], 1);
        if (q < S_SAMPLE + M_TILE) g_sel[q] = i;
    } else if (p == P) {
        g_flag[i] = 0;
        int e = atomicAdd(&g_counters[C_EQ], 1);
        if (e < EQCAP) g_eqList[e] = i;
    } else {
        g_flag[i] = 0;
    }
}

// ---------------------------------------------------------------------------
// eq_resolve: O(n) in-bin radix descent over the eq list (single block).
// Finds the exact 32-bit threshold via two 256-bin histograms, then selects
// key > T32 plus lowest-index ties at T32.
// ---------------------------------------------------------------------------
__global__ void eq_resolve_kernel() {
    __shared__ unsigned hist[256];
    __shared__ unsigned suf[256];
    __shared__ unsigned sb, sneed;
    __shared__ int tie_idx[64];
    __shared__ unsigned tie_cnt;
    int t = threadIdx.x;
    int n = g_counters[C_EQ];
    if (n > EQCAP) n = EQCAP;
    unsigned d = (unsigned)g_counters[C_REM];

    // ---- level 2: bits [15:8] ----
    hist[t] = 0;
    if (t == 0) tie_cnt = 0;
    __syncthreads();
    for (int j = t; j < n; j += 256)
        atomicAdd(&hist[(g_keys[g_eqList[j]] >> 8) & 255u], 1u);
    __syncthreads();
    suf[t] = hist[t];
    __syncthreads();
#pragma unroll
    for (int off = 1; off < 256; off <<= 1) {
        unsigned v = (t + off < 256) ? suf[t + off] : 0u;
        __syncthreads();
        suf[t] += v;
        __syncthreads();
    }
    {
        unsigned above = (t < 255) ? suf[t + 1] : 0u;
        if (suf[t] >= d && above < d) { sb = (unsigned)t; sneed = d - above; }
    }
    __syncthreads();
    unsigned b2 = sb, need3 = sneed;

    // ---- level 3: bits [7:0] among keys with bits[15:8]==b2 ----
    hist[t] = 0;
    __syncthreads();
    for (int j = t; j < n; j += 256) {
        unsigned k = g_keys[g_eqList[j]];
        if (((k >> 8) & 255u) == b2) atomicAdd(&hist[k & 255u], 1u);
    }
    __syncthreads();
    suf[t] = hist[t];
    __syncthreads();
#pragma unroll
    for (int off = 1; off < 256; off <<= 1) {
        unsigned v = (t + off < 256) ? suf[t + off] : 0u;
        __syncthreads();
        suf[t] += v;
        __syncthreads();
    }
    {
        unsigned above = (t < 255) ? suf[t + 1] : 0u;
        if (suf[t] >= need3 && above < need3) { sb = (unsigned)t; sneed = need3 - above; }
    }
    __syncthreads();
    unsigned T32 = (g_P16 << 16) | (b2 << 8) | sb;
    unsigned ties_needed = sneed;

    // ---- selection pass ----
    for (int j = t; j < n; j += 256) {
        int idx = g_eqList[j];
        unsigned k = g_keys[idx];
        if (k > T32) {
            g_flag[idx] = 1;
            int q = atomicAdd(&g_counters[C_SEL], 1);
            if (q < S_SAMPLE + M_TILE) g_sel[q] = idx;
        } else if (k == T32) {
            unsigned e = atomicAdd(&tie_cnt, 1u);
            if (e < 64) tie_idx[e] = idx;
        }
    }
    __syncthreads();
    // exact-key ties: take the ties_needed lowest indices (lax.top_k order)
    int m = (tie_cnt < 64u) ? (int)tie_cnt : 64;
    if (t < m) {
        int idx = tie_idx[t];
        int rank = 0;
        for (int j = 0; j < m; j++) rank += (tie_idx[j] < idx) ? 1 : 0;
        if (rank < (int)ties_needed) {
            g_flag[idx] = 1;
            int q = atomicAdd(&g_counters[C_SEL], 1);
            if (q < S_SAMPLE + M_TILE) g_sel[q] = idx;
        }
    }
}

// ---------------------------------------------------------------------------
// fused GEMM + zero (roles interleaved by blockIdx for overlap).
// GEMM: M=64 gathered rows x N=256, K=256; A full-K resident (f16),
// B in 32-k chunks; 8 warps x (2x8) m16n8k16 HMMA.
// ---------------------------------------------------------------------------
#define A_STRIDE 264
#define B_STRIDE 264
#define AS_BYTES (M_TILE * A_STRIDE * 2)
#define BS_BYTES (32 * B_STRIDE * 2)
#define SMEM_DYN (AS_BYTES + BS_BYTES)

__device__ __forceinline__ uint32_t smem_u32(const void* p) {
    uint32_t a;
    asm("{ .reg .u64 t; cvta.to.shared.u64 t, %1; cvt.u32.u64 %0, t; }"
        : "=r"(a) : "l"(p));
    return a;
}

__global__ void __launch_bounds__(256, 2) fused_kernel(
    const float* __restrict__ x, const float* __restrict__ bias,
    float* __restrict__ out) {
    extern __shared__ __align__(16) char dsm[];
    __shared__ int rows_s[M_TILE];

    int bid = blockIdx.x;
    int tid = threadIdx.x;
    int wid = tid >> 5;
    int lane = tid & 31;

    int gemm_id = -1, zero_id;
    if (bid < 2 * NBLK) {
        if ((bid & 1) == 0) gemm_id = bid >> 1;
        else zero_id = bid >> 1;
    } else {
        zero_id = NBLK + (bid - 2 * NBLK);
    }

    if (gemm_id < 0) {
        int gw = zero_id * 8 + wid;
        float4 z = make_float4(0.f, 0.f, 0.f, 0.f);
        for (int row = gw; row < N_NODES; row += NZERO * 8) {
            if (!g_flag[row]) {
                float4* p = (float4*)(out + (size_t)row * OUT_C);
                p[lane] = z;
                p[lane + 32] = z;
            }
        }
        return;
    }

    __half* As = (__half*)dsm;
    __half* Bs = (__half*)(dsm + AS_BYTES);
    const uint32_t As_base = smem_u32(As);
    const uint32_t Bs_base = smem_u32(Bs);

    int r0 = gemm_id * M_TILE;
    if (tid < M_TILE) {
        int rr = r0 + tid;
        rows_s[tid] = g_sel[(rr < S_SAMPLE) ? rr : r0];
    }
    __syncthreads();

    // A: full-K gather, f32 -> f16 (4 threads per row)
    {
        int row = tid >> 2;
        int quarter = tid & 3;
        const float4* src = (const float4*)(x + (size_t)rows_s[row] * IN_C);
        __half* dstrow = As + row * A_STRIDE;
#pragma unroll
        for (int j = 0; j < 16; j++) {
            int c4 = quarter + 4 * j;
            float4 v = src[c4];
            __half2 h0 = __floats2half2_rn(v.x, v.y);
            __half2 h1 = __floats2half2_rn(v.z, v.w);
            uint2 pk;
            pk.x = *(unsigned*)&h0;
            pk.y = *(unsigned*)&h1;
            *(uint2*)(dstrow + c4 * 4) = pk;
        }
    }

    int m_half = wid & 1;
    int n_quad = wid >> 1;
    float acc[2][8][4];
#pragma unroll
    for (int mt = 0; mt < 2; mt++)
#pragma unroll
        for (int nt = 0; nt < 8; nt++)
#pragma unroll
            for (int q = 0; q < 4; q++) acc[mt][nt][q] = 0.f;

    int b_krow = tid >> 3;
    int b_seg = (tid & 7) * 32;

    for (int kc = 0; kc < 8; kc++) {
        __syncthreads();
        {
            const uint4* src = (const uint4*)&g_wh[(kc * 32 + b_krow) * 128 + b_seg / 2];
            uint4* dst = (uint4*)&Bs[b_krow * B_STRIDE + b_seg];
            dst[0] = src[0];
            dst[1] = src[1];
            dst[2] = src[2];
            dst[3] = src[3];
        }
        __syncthreads();

#pragma unroll
        for (int ks = 0; ks < 2; ks++) {
            uint32_t af[2][4];
#pragma unroll
            for (int mt = 0; mt < 2; mt++) {
                int row = m_half * 32 + mt * 16 + (lane & 15);
                int col = kc * 32 + ks * 16 + (lane >> 4) * 8;
                uint32_t addr = As_base + (row * A_STRIDE + col) * 2;
                asm volatile(
                    "ldmatrix.sync.aligned.m8n8.x4.shared.b16 {%0,%1,%2,%3}, [%4];"
                    : "=r"(af[mt][0]), "=r"(af[mt][1]),
                      "=r"(af[mt][2]), "=r"(af[mt][3]) : "r"(addr));
            }
            uint32_t bf[8][2];
#pragma unroll
            for (int nt = 0; nt < 8; nt++) {
                int krow = ks * 16 + (lane & 15);
                int ncol = n_quad * 64 + nt * 8;
                uint32_t addr = Bs_base + (krow * B_STRIDE + ncol) * 2;
                asm volatile(
                    "ldmatrix.sync.aligned.m8n8.x2.trans.shared.b16 {%0,%1}, [%2];"
                    : "=r"(bf[nt][0]), "=r"(bf[nt][1]) : "r"(addr));
            }
#pragma unroll
            for (int mt = 0; mt < 2; mt++)
#pragma unroll
                for (int nt = 0; nt < 8; nt++) {
                    asm volatile(
                        "mma.sync.aligned.m16n8k16.row.col.f32.f16.f16.f32 "
                        "{%0,%1,%2,%3}, {%4,%5,%6,%7}, {%8,%9}, {%0,%1,%2,%3};"
                        : "+f"(acc[mt][nt][0]), "+f"(acc[mt][nt][1]),
                          "+f"(acc[mt][nt][2]), "+f"(acc[mt][nt][3])
                        : "r"(af[mt][0]), "r"(af[mt][1]),
                          "r"(af[mt][2]), "r"(af[mt][3]),
                          "r"(bf[nt][0]), "r"(bf[nt][1]));
                }
        }
    }

    const float scale = 5.0f;
    int qr = lane >> 2;
    int qc = (lane & 3) * 2;
#pragma unroll
    for (int mt = 0; mt < 2; mt++) {
        int lrow_lo = m_half * 32 + mt * 16 + qr;
        int g_lo = rows_s[lrow_lo];
        int g_hi = rows_s[lrow_lo + 8];
        float* row_lo = out + (size_t)g_lo * OUT_C;
        float* row_hi = out + (size_t)g_hi * OUT_C;
#pragma unroll
        for (int nt = 0; nt < 8; nt++) {
            int col = n_quad * 64 + nt * 8 + qc;
            float b0 = bias[col], b1 = bias[col + 1];
            *(float2*)(row_lo + col) = make_float2(
                (acc[mt][nt][0] + b0) * scale, (acc[mt][nt][1] + b1) * scale);
            *(float2*)(row_hi + col) = make_float2(
                (acc[mt][nt][2] + b0) * scale, (acc[mt][nt][3] + b1) * scale);
        }
    }
}

// ---------------------------------------------------------------------------
// Launch
// ---------------------------------------------------------------------------
extern "C" void kernel_launch(void* const* d_in, const int* in_sizes, int n_in,
                              void* d_out, int out_size) {
    const float* x = nullptr;
    const float* w = nullptr;
    const float* bias = nullptr;
    const float* imp = nullptr;
    for (int i = 0; i < n_in; i++) {
        switch (in_sizes[i]) {
            case 128000000: x = (const float*)d_in[i]; break;
            case 65536:     w = (const float*)d_in[i]; break;
            case 256:       bias = (const float*)d_in[i]; break;
            case 500000:    imp = (const float*)d_in[i]; break;
            default: break;  // edge_index unused
        }
    }
    float* out = (float*)d_out;
    (void)out_size;

    cudaFuncSetAttribute(fused_kernel,
                         cudaFuncAttributeMaxDynamicSharedMemorySize, SMEM_DYN);

    prep_kernel<<<128, 256>>>(w);
    score_kernel<<<(N_NODES + 255) / 256, 256>>>(imp);
    pick16_kernel<<<1, 256>>>();
    flag_kernel<<<(N_NODES + 255) / 256, 256>>>();
    eq_resolve_kernel<<<1, 256>>>();
    fused_kernel<<<NTOT, 256, SMEM_DYN>>>(x, bias, out);
}

// round 9
// speedup vs baseline: 33.9785x; 1.1423x over previous
#include <cuda_runtime.h>
#include <cuda_fp16.h>
#include <cstdint>

// ---------------------------------------------------------------------------
// Problem constants
// ---------------------------------------------------------------------------
#define N_NODES 500000
#define S_SAMPLE 100000
#define EQCAP 32768
#define OUT_C 256
#define IN_C 256
#define M_TILE 64
#define NBLK ((S_SAMPLE + M_TILE - 1) / M_TILE)   // 1563

// libdevice accurate log (immune to fast-math logf substitution)
extern "C" __device__ float __nv_logf(float);

// ---------------------------------------------------------------------------
// Device scratch
// ---------------------------------------------------------------------------
__device__ unsigned g_keys[N_NODES];
__device__ unsigned char g_flag[N_NODES];
__device__ int g_sel[S_SAMPLE + M_TILE];
__device__ uint2 g_eqPair[EQCAP];   // (key, idx)
__device__ unsigned g_h16[65536];
__device__ unsigned g_c256[256];
__device__ unsigned g_P16;
__device__ int g_counters[4];
__device__ unsigned g_wh[32768];    // w as f16 pairs, [k][n] row-major
#define C_SEL 0
#define C_EQ 1
#define C_REM 2

// ---------------------------------------------------------------------------
// Threefry-2x32, partitionable: x0=0, x1=i, key=(0,42); draw = out0 ^ out1
// (validated exact, round 4)
// ---------------------------------------------------------------------------
__device__ __forceinline__ unsigned rotl32(unsigned x, int r) {
    return (x << r) | (x >> (32 - r));
}
__device__ __forceinline__ unsigned threefry_bits(unsigned i) {
    const unsigned ks0 = 0u, ks1 = 42u;
    const unsigned ks2 = 0x1BD11BDAu ^ ks0 ^ ks1;
    unsigned x0 = 0u + ks0;
    unsigned x1 = i + ks1;
#define TF_R4(a, b, c, d)                                   \
    x0 += x1; x1 = rotl32(x1, a); x1 ^= x0;                 \
    x0 += x1; x1 = rotl32(x1, b); x1 ^= x0;                 \
    x0 += x1; x1 = rotl32(x1, c); x1 ^= x0;                 \
    x0 += x1; x1 = rotl32(x1, d); x1 ^= x0;
    TF_R4(13, 15, 26, 6)  x0 += ks1; x1 += ks2 + 1u;
    TF_R4(17, 29, 16, 24) x0 += ks2; x1 += ks0 + 2u;
    TF_R4(13, 15, 26, 6)  x0 += ks0; x1 += ks1 + 3u;
    TF_R4(17, 29, 16, 24) x0 += ks1; x1 += ks2 + 4u;
    TF_R4(13, 15, 26, 6)  x0 += ks2; x1 += ks0 + 5u;
#undef TF_R4
    return x0 ^ x1;
}
__device__ __forceinline__ unsigned f2key(float f) {
    unsigned b = __float_as_uint(f);
    return (b & 0x80000000u) ? ~b : (b | 0x80000000u);
}

// ---------------------------------------------------------------------------
// prep: zero hists/counters + convert w to f16
// ---------------------------------------------------------------------------
__global__ void prep_kernel(const float* __restrict__ w) {
    int t = blockIdx.x * blockDim.x + threadIdx.x;   // 32768 threads
    g_h16[t] = 0;
    g_h16[t + 32768] = 0;
    if (t < 256) g_c256[t] = 0;
    if (t < 4) g_counters[t] = 0;
    float2 v = ((const float2*)w)[t];
    __half2 h = __floats2half2_rn(v.x, v.y);
    g_wh[t] = *(unsigned*)&h;
}

// ---------------------------------------------------------------------------
// score: keys + 16-bit histogram (+ shared-aggregated coarse 256)
// ---------------------------------------------------------------------------
__global__ void score_kernel(const float* __restrict__ imp) {
    __shared__ unsigned sh[256];
    int tid = threadIdx.x;
    sh[tid] = 0;
    __syncthreads();
    int i = blockIdx.x * blockDim.x + tid;
    if (i < N_NODES) {
        unsigned bits = threefry_bits((unsigned)i);
        float f = __uint_as_float((bits >> 9) | 0x3F800000u) - 1.0f;
        float u = f + 1.17549435e-38f;
        float g = -__nv_logf(-__nv_logf(u));
        unsigned k = f2key(__nv_logf(imp[i]) + g);
        g_keys[i] = k;
        atomicAdd(&sh[k >> 24], 1u);
        atomicAdd(&g_h16[k >> 16], 1u);
    }
    __syncthreads();
    if (sh[tid]) atomicAdd(&g_c256[tid], sh[tid]);
}

// ---------------------------------------------------------------------------
// pick16: one block; exact top-16-bit threshold via two suffix scans
// ---------------------------------------------------------------------------
__global__ void pick16_kernel() {
    __shared__ unsigned suf[256];
    __shared__ unsigned sb0, sneed;
    int t = threadIdx.x;
    suf[t] = g_c256[t];
    __syncthreads();
#pragma unroll
    for (int off = 1; off < 256; off <<= 1) {
        unsigned v = (t + off < 256) ? suf[t + off] : 0u;
        __syncthreads();
        suf[t] += v;
        __syncthreads();
    }
    {
        unsigned need = S_SAMPLE;
        unsigned above = (t < 255) ? suf[t + 1] : 0u;
        if (suf[t] >= need && above < need) { sb0 = (unsigned)t; sneed = need - above; }
    }
    __syncthreads();
    unsigned b0 = sb0, need2 = sneed;
    suf[t] = g_h16[b0 * 256 + t];
    __syncthreads();
#pragma unroll
    for (int off = 1; off < 256; off <<= 1) {
        unsigned v = (t + off < 256) ? suf[t + off] : 0u;
        __syncthreads();
        suf[t] += v;
        __syncthreads();
    }
    {
        unsigned above = (t < 255) ? suf[t + 1] : 0u;
        if (suf[t] >= need2 && above < need2) {
            g_P16 = (b0 << 8) | (unsigned)t;
            g_counters[C_REM] = (int)(need2 - above);
        }
    }
}

// ---------------------------------------------------------------------------
// flag: one scan; block-aggregated compaction (1 global atomic per list/block)
// ---------------------------------------------------------------------------
__global__ void flag_kernel() {
    __shared__ int s_wsel[8], s_weq[8];
    __shared__ int s_osel[8], s_oeq[8];
    __shared__ int s_bsel, s_beq;
    int tid = threadIdx.x;
    int wid = tid >> 5;
    int lane = tid & 31;
    int i = blockIdx.x * blockDim.x + tid;
    bool valid = (i < N_NODES);
    unsigned k = valid ? g_keys[i] : 0u;
    unsigned p = k >> 16;
    unsigned P = g_P16;
    bool sel = valid && (p > P);
    bool eq = valid && (p == P);
    if (valid) g_flag[i] = sel ? 1 : 0;

    unsigned mSel = __ballot_sync(0xFFFFFFFFu, sel);
    unsigned mEq = __ballot_sync(0xFFFFFFFFu, eq);
    if (lane == 0) { s_wsel[wid] = __popc(mSel); s_weq[wid] = __popc(mEq); }
    __syncthreads();
    if (tid == 0) {
        int accS = 0, accE = 0;
#pragma unroll
        for (int wdx = 0; wdx < 8; wdx++) {
            s_osel[wdx] = accS; accS += s_wsel[wdx];
            s_oeq[wdx] = accE; accE += s_weq[wdx];
        }
        s_bsel = accS ? atomicAdd(&g_counters[C_SEL], accS) : 0;
        s_beq = accE ? atomicAdd(&g_counters[C_EQ], accE) : 0;
    }
    __syncthreads();
    unsigned lt = (1u << lane) - 1u;
    if (sel) {
        int pos = s_bsel + s_osel[wid] + __popc(mSel & lt);
        if (pos < S_SAMPLE + M_TILE) g_sel[pos] = i;
    }
    if (eq) {
        int pos = s_beq + s_oeq[wid] + __popc(mEq & lt);
        if (pos < EQCAP) g_eqPair[pos] = make_uint2(k, (unsigned)i);
    }
}

// ---------------------------------------------------------------------------
// eq_resolve: O(n) in-bin radix descent over (key, idx) pairs — linear reads.
// ---------------------------------------------------------------------------
__global__ void eq_resolve_kernel() {
    __shared__ unsigned hist[256];
    __shared__ unsigned suf[256];
    __shared__ unsigned sb, sneed;
    __shared__ int tie_idx[64];
    __shared__ unsigned tie_cnt;
    int t = threadIdx.x;
    int n = g_counters[C_EQ];
    if (n > EQCAP) n = EQCAP;
    unsigned d = (unsigned)g_counters[C_REM];

    // level 2: bits [15:8]
    hist[t] = 0;
    if (t == 0) tie_cnt = 0;
    __syncthreads();
    for (int j = t; j < n; j += 256)
        atomicAdd(&hist[(g_eqPair[j].x >> 8) & 255u], 1u);
    __syncthreads();
    suf[t] = hist[t];
    __syncthreads();
#pragma unroll
    for (int off = 1; off < 256; off <<= 1) {
        unsigned v = (t + off < 256) ? suf[t + off] : 0u;
        __syncthreads();
        suf[t] += v;
        __syncthreads();
    }
    {
        unsigned above = (t < 255) ? suf[t + 1] : 0u;
        if (suf[t] >= d && above < d) { sb = (unsigned)t; sneed = d - above; }
    }
    __syncthreads();
    unsigned b2 = sb, need3 = sneed;

    // level 3: bits [7:0] among keys with bits[15:8]==b2
    hist[t] = 0;
    __syncthreads();
    for (int j = t; j < n; j += 256) {
        unsigned k = g_eqPair[j].x;
        if (((k >> 8) & 255u) == b2) atomicAdd(&hist[k & 255u], 1u);
    }
    __syncthreads();
    suf[t] = hist[t];
    __syncthreads();
#pragma unroll
    for (int off = 1; off < 256; off <<= 1) {
        unsigned v = (t + off < 256) ? suf[t + off] : 0u;
        __syncthreads();
        suf[t] += v;
        __syncthreads();
    }
    {
        unsigned above = (t < 255) ? suf[t + 1] : 0u;
        if (suf[t] >= need3 && above < need3) { sb = (unsigned)t; sneed = need3 - above; }
    }
    __syncthreads();
    unsigned T32 = (g_P16 << 16) | (b2 << 8) | sb;
    unsigned ties_needed = sneed;

    // selection pass (linear)
    for (int j = t; j < n; j += 256) {
        uint2 pr = g_eqPair[j];
        if (pr.x > T32) {
            g_flag[pr.y] = 1;
            int q = atomicAdd(&g_counters[C_SEL], 1);
            if (q < S_SAMPLE + M_TILE) g_sel[q] = (int)pr.y;
        } else if (pr.x == T32) {
            unsigned e = atomicAdd(&tie_cnt, 1u);
            if (e < 64) tie_idx[e] = (int)pr.y;
        }
    }
    __syncthreads();
    int m = (tie_cnt < 64u) ? (int)tie_cnt : 64;
    if (t < m) {
        int idx = tie_idx[t];
        int rank = 0;
        for (int j = 0; j < m; j++) rank += (tie_idx[j] < idx) ? 1 : 0;
        if (rank < (int)ties_needed) {
            g_flag[idx] = 1;
            int q = atomicAdd(&g_counters[C_SEL], 1);
            if (q < S_SAMPLE + M_TILE) g_sel[q] = idx;
        }
    }
}

// ---------------------------------------------------------------------------
// zero: unselected rows (no smem -> full occupancy, pure BW)
// ---------------------------------------------------------------------------
__global__ void zero_kernel(float* __restrict__ out) {
    int gw = (blockIdx.x * blockDim.x + threadIdx.x) >> 5;
    int lane = threadIdx.x & 31;
    int nw = (gridDim.x * blockDim.x) >> 5;
    float4 z = make_float4(0.f, 0.f, 0.f, 0.f);
    for (int row = gw; row < N_NODES; row += nw) {
        if (!g_flag[row]) {
            float4* p = (float4*)(out + (size_t)row * OUT_C);
            p[lane] = z;
            p[lane + 32] = z;
        }
    }
}

// ---------------------------------------------------------------------------
// HMMA GEMM (measured-good, unchanged): M=64 gathered rows x N=256, K=256.
// A full-K resident (f16), B in 32-k chunks; 8 warps x (2x8) m16n8k16.
// ---------------------------------------------------------------------------
#define A_STRIDE 264
#define B_STRIDE 264
#define AS_BYTES (M_TILE * A_STRIDE * 2)
#define BS_BYTES (32 * B_STRIDE * 2)
#define SMEM_DYN (AS_BYTES + BS_BYTES)

__device__ __forceinline__ uint32_t smem_u32(const void* p) {
    uint32_t a;
    asm("{ .reg .u64 t; cvta.to.shared.u64 t, %1; cvt.u32.u64 %0, t; }"
        : "=r"(a) : "l"(p));
    return a;
}

__global__ void __launch_bounds__(256, 2) gemm_kernel(
    const float* __restrict__ x, const float* __restrict__ bias,
    float* __restrict__ out) {
    extern __shared__ __align__(16) char dsm[];
    __shared__ int rows_s[M_TILE];

    int tid = threadIdx.x;
    int wid = tid >> 5;
    int lane = tid & 31;

    __half* As = (__half*)dsm;
    __half* Bs = (__half*)(dsm + AS_BYTES);
    const uint32_t As_base = smem_u32(As);
    const uint32_t Bs_base = smem_u32(Bs);

    int r0 = blockIdx.x * M_TILE;
    if (tid < M_TILE) {
        int rr = r0 + tid;
        rows_s[tid] = g_sel[(rr < S_SAMPLE) ? rr : r0];
    }
    __syncthreads();

    // A: full-K gather, f32 -> f16 (4 threads per row)
    {
        int row = tid >> 2;
        int quarter = tid & 3;
        const float4* src = (const float4*)(x + (size_t)rows_s[row] * IN_C);
        __half* dstrow = As + row * A_STRIDE;
#pragma unroll
        for (int j = 0; j < 16; j++) {
            int c4 = quarter + 4 * j;
            float4 v = src[c4];
            __half2 h0 = __floats2half2_rn(v.x, v.y);
            __half2 h1 = __floats2half2_rn(v.z, v.w);
            uint2 pk;
            pk.x = *(unsigned*)&h0;
            pk.y = *(unsigned*)&h1;
            *(uint2*)(dstrow + c4 * 4) = pk;
        }
    }

    int m_half = wid & 1;
    int n_quad = wid >> 1;
    float acc[2][8][4];
#pragma unroll
    for (int mt = 0; mt < 2; mt++)
#pragma unroll
        for (int nt = 0; nt < 8; nt++)
#pragma unroll
            for (int q = 0; q < 4; q++) acc[mt][nt][q] = 0.f;

    int b_krow = tid >> 3;
    int b_seg = (tid & 7) * 32;

    for (int kc = 0; kc < 8; kc++) {
        __syncthreads();
        {
            const uint4* src = (const uint4*)&g_wh[(kc * 32 + b_krow) * 128 + b_seg / 2];
            uint4* dst = (uint4*)&Bs[b_krow * B_STRIDE + b_seg];
            dst[0] = src[0];
            dst[1] = src[1];
            dst[2] = src[2];
            dst[3] = src[3];
        }
        __syncthreads();

#pragma unroll
        for (int ks = 0; ks < 2; ks++) {
            uint32_t af[2][4];
#pragma unroll
            for (int mt = 0; mt < 2; mt++) {
                int row = m_half * 32 + mt * 16 + (lane & 15);
                int col = kc * 32 + ks * 16 + (lane >> 4) * 8;
                uint32_t addr = As_base + (row * A_STRIDE + col) * 2;
                asm volatile(
                    "ldmatrix.sync.aligned.m8n8.x4.shared.b16 {%0,%1,%2,%3}, [%4];"
                    : "=r"(af[mt][0]), "=r"(af[mt][1]),
                      "=r"(af[mt][2]), "=r"(af[mt][3]) : "r"(addr));
            }
            uint32_t bf[8][2];
#pragma unroll
            for (int nt = 0; nt < 8; nt++) {
                int krow = ks * 16 + (lane & 15);
                int ncol = n_quad * 64 + nt * 8;
                uint32_t addr = Bs_base + (krow * B_STRIDE + ncol) * 2;
                asm volatile(
                    "ldmatrix.sync.aligned.m8n8.x2.trans.shared.b16 {%0,%1}, [%2];"
                    : "=r"(bf[nt][0]), "=r"(bf[nt][1]) : "r"(addr));
            }
#pragma unroll
            for (int mt = 0; mt < 2; mt++)
#pragma unroll
                for (int nt = 0; nt < 8; nt++) {
                    asm volatile(
                        "mma.sync.aligned.m16n8k16.row.col.f32.f16.f16.f32 "
                        "{%0,%1,%2,%3}, {%4,%5,%6,%7}, {%8,%9}, {%0,%1,%2,%3};"
                        : "+f"(acc[mt][nt][0]), "+f"(acc[mt][nt][1]),
                          "+f"(acc[mt][nt][2]), "+f"(acc[mt][nt][3])
                        : "r"(af[mt][0]), "r"(af[mt][1]),
                          "r"(af[mt][2]), "r"(af[mt][3]),
                          "r"(bf[nt][0]), "r"(bf[nt][1]));
                }
        }
    }

    const float scale = 5.0f;
    int qr = lane >> 2;
    int qc = (lane & 3) * 2;
#pragma unroll
    for (int mt = 0; mt < 2; mt++) {
        int lrow_lo = m_half * 32 + mt * 16 + qr;
        int g_lo = rows_s[lrow_lo];
        int g_hi = rows_s[lrow_lo + 8];
        float* row_lo = out + (size_t)g_lo * OUT_C;
        float* row_hi = out + (size_t)g_hi * OUT_C;
#pragma unroll
        for (int nt = 0; nt < 8; nt++) {
            int col = n_quad * 64 + nt * 8 + qc;
            float b0 = bias[col], b1 = bias[col + 1];
            *(float2*)(row_lo + col) = make_float2(
                (acc[mt][nt][0] + b0) * scale, (acc[mt][nt][1] + b1) * scale);
            *(float2*)(row_hi + col) = make_float2(
                (acc[mt][nt][2] + b0) * scale, (acc[mt][nt][3] + b1) * scale);
        }
    }
}

// ---------------------------------------------------------------------------
// Launch
// ---------------------------------------------------------------------------
extern "C" void kernel_launch(void* const* d_in, const int* in_sizes, int n_in,
                              void* d_out, int out_size) {
    const float* x = nullptr;
    const float* w = nullptr;
    const float* bias = nullptr;
    const float* imp = nullptr;
    for (int i = 0; i < n_in; i++) {
        switch (in_sizes[i]) {
            case 128000000: x = (const float*)d_in[i]; break;
            case 65536:     w = (const float*)d_in[i]; break;
            case 256:       bias = (const float*)d_in[i]; break;
            case 500000:    imp = (const float*)d_in[i]; break;
            default: break;  // edge_index unused
        }
    }
    float* out = (float*)d_out;
    (void)out_size;

    cudaFuncSetAttribute(gemm_kernel,
                         cudaFuncAttributeMaxDynamicSharedMemorySize, SMEM_DYN);

    prep_kernel<<<128, 256>>>(w);
    score_kernel<<<(N_NODES + 255) / 256, 256>>>(imp);
    pick16_kernel<<<1, 256>>>();
    flag_kernel<<<(N_NODES + 255) / 256, 256>>>();
    eq_resolve_kernel<<<1, 256>>>();
    zero_kernel<<<1024, 256>>>(out);
    gemm_kernel<<<NBLK, 256, SMEM_DYN>>>(x, bias, out);
}

// round 10
// speedup vs baseline: 47.3457x; 1.3934x over previous
#include <cuda_runtime.h>
#include <cuda_fp16.h>
#include <cstdint>

// ---------------------------------------------------------------------------
// Problem constants
// ---------------------------------------------------------------------------
#define N_NODES 500000
#define S_SAMPLE 100000
#define EQCAP 32768
#define OUT_C 256
#define IN_C 256
#define M_TILE 64
#define NBLK ((S_SAMPLE + M_TILE - 1) / M_TILE)   // 1563

// libdevice accurate log (immune to fast-math logf substitution)
extern "C" __device__ float __nv_logf(float);

// ---------------------------------------------------------------------------
// Device scratch
// ---------------------------------------------------------------------------
__device__ unsigned g_keys[N_NODES];
__device__ unsigned char g_flag[N_NODES];
__device__ int g_sel[S_SAMPLE + M_TILE];
__device__ uint2 g_eqPair[EQCAP];   // (key, idx)
__device__ unsigned g_c256[256];    // coarse hist: bits [31:24]
__device__ unsigned g_m256[256];    // mid hist: bits [23:16] within b0
__device__ unsigned g_B0;
__device__ unsigned g_P16;
__device__ int g_counters[4];
__device__ unsigned g_done[2];
__device__ unsigned g_wh[32768];    // w as f16 pairs, [k][n] row-major
#define C_SEL 0
#define C_EQ 1
#define C_REM 2

// ---------------------------------------------------------------------------
// Threefry-2x32, partitionable: x0=0, x1=i, key=(0,42); draw = out0 ^ out1
// (validated exact, round 4)
// ---------------------------------------------------------------------------
__device__ __forceinline__ unsigned rotl32(unsigned x, int r) {
    return (x << r) | (x >> (32 - r));
}
__device__ __forceinline__ unsigned threefry_bits(unsigned i) {
    const unsigned ks0 = 0u, ks1 = 42u;
    const unsigned ks2 = 0x1BD11BDAu ^ ks0 ^ ks1;
    unsigned x0 = 0u + ks0;
    unsigned x1 = i + ks1;
#define TF_R4(a, b, c, d)                                   \
    x0 += x1; x1 = rotl32(x1, a); x1 ^= x0;                 \
    x0 += x1; x1 = rotl32(x1, b); x1 ^= x0;                 \
    x0 += x1; x1 = rotl32(x1, c); x1 ^= x0;                 \
    x0 += x1; x1 = rotl32(x1, d); x1 ^= x0;
    TF_R4(13, 15, 26, 6)  x0 += ks1; x1 += ks2 + 1u;
    TF_R4(17, 29, 16, 24) x0 += ks2; x1 += ks0 + 2u;
    TF_R4(13, 15, 26, 6)  x0 += ks0; x1 += ks1 + 3u;
    TF_R4(17, 29, 16, 24) x0 += ks1; x1 += ks2 + 4u;
    TF_R4(13, 15, 26, 6)  x0 += ks2; x1 += ks0 + 5u;
#undef TF_R4
    return x0 ^ x1;
}
__device__ __forceinline__ unsigned f2key(float f) {
    unsigned b = __float_as_uint(f);
    return (b & 0x80000000u) ? ~b : (b | 0x80000000u);
}

// ---------------------------------------------------------------------------
// suffix-scan pick over a 256-bin hist (in-block); returns via pointers
// ---------------------------------------------------------------------------
__device__ void pick256(const unsigned* hist, unsigned need,
                        unsigned* out_bin, unsigned* out_rem, unsigned* suf) {
    int t = threadIdx.x;
    suf[t] = hist[t];
    __syncthreads();
#pragma unroll
    for (int off = 1; off < 256; off <<= 1) {
        unsigned v = (t + off < 256) ? suf[t + off] : 0u;
        __syncthreads();
        suf[t] += v;
        __syncthreads();
    }
    unsigned above = (t < 255) ? suf[t + 1] : 0u;
    if (suf[t] >= need && above < need) {
        *out_bin = (unsigned)t;
        *out_rem = need - above;
        __threadfence();
    }
    __syncthreads();
}

// ---------------------------------------------------------------------------
// prep: zero counters + convert w to f16
// ---------------------------------------------------------------------------
__global__ void prep_kernel(const float* __restrict__ w) {
    int t = blockIdx.x * blockDim.x + threadIdx.x;   // 32768 threads
    if (t < 256) { g_c256[t] = 0; g_m256[t] = 0; }
    if (t < 4) g_counters[t] = 0;
    if (t < 2) g_done[t] = 0;
    float2 v = ((const float2*)w)[t];
    __half2 h = __floats2half2_rn(v.x, v.y);
    g_wh[t] = *(unsigned*)&h;
}

// ---------------------------------------------------------------------------
// score: keys + shared coarse hist (bits[31:24]) + fused pick8 in tail block
// ---------------------------------------------------------------------------
__global__ void score_kernel(const float* __restrict__ imp) {
    __shared__ unsigned sh[256];
    __shared__ unsigned is_last;
    int tid = threadIdx.x;
    sh[tid] = 0;
    if (tid == 0) is_last = 0;
    __syncthreads();
    int i = blockIdx.x * blockDim.x + tid;
    if (i < N_NODES) {
        unsigned bits = threefry_bits((unsigned)i);
        float f = __uint_as_float((bits >> 9) | 0x3F800000u) - 1.0f;
        float u = f + 1.17549435e-38f;
        float g = -__nv_logf(-__nv_logf(u));
        unsigned k = f2key(__nv_logf(imp[i]) + g);
        g_keys[i] = k;
        atomicAdd(&sh[k >> 24], 1u);
    }
    __syncthreads();
    if (sh[tid]) atomicAdd(&g_c256[tid], sh[tid]);
    __threadfence();
    __syncthreads();
    if (tid == 0) {
        unsigned old = atomicAdd(&g_done[0], 1u);
        if (old == gridDim.x - 1) is_last = 1;
    }
    __syncthreads();
    if (is_last) {
        // pick top-8-bit bin containing rank S
        pick256(g_c256, S_SAMPLE, &g_B0, (unsigned*)&g_counters[C_REM], sh);
    }
}

// ---------------------------------------------------------------------------
// hist2: bits[23:16] hist among keys with top byte == B0 (+ fused pick16)
// ---------------------------------------------------------------------------
__global__ void hist2_kernel() {
    __shared__ unsigned sh[256];
    __shared__ unsigned is_last;
    int tid = threadIdx.x;
    sh[tid] = 0;
    if (tid == 0) is_last = 0;
    __syncthreads();
    unsigned b0 = g_B0;
    int stride = gridDim.x * blockDim.x;
    for (int i = blockIdx.x * blockDim.x + tid; i < N_NODES; i += stride) {
        unsigned k = g_keys[i];
        if ((k >> 24) == b0) atomicAdd(&sh[(k >> 16) & 255u], 1u);
    }
    __syncthreads();
    if (sh[tid]) atomicAdd(&g_m256[tid], sh[tid]);
    __threadfence();
    __syncthreads();
    if (tid == 0) {
        unsigned old = atomicAdd(&g_done[1], 1u);
        if (old == gridDim.x - 1) is_last = 1;
    }
    __syncthreads();
    if (is_last) {
        __shared__ unsigned sbin, srem;
        pick256(g_m256, (unsigned)g_counters[C_REM], &sbin, &srem, sh);
        if (tid == 0) {
            g_P16 = (g_B0 << 8) | sbin;
            g_counters[C_REM] = (int)srem;
        }
    }
}

// ---------------------------------------------------------------------------
// flag: one scan; block-aggregated compaction (1 global atomic per list/block)
// ---------------------------------------------------------------------------
__global__ void flag_kernel() {
    __shared__ int s_wsel[8], s_weq[8];
    __shared__ int s_osel[8], s_oeq[8];
    __shared__ int s_bsel, s_beq;
    int tid = threadIdx.x;
    int wid = tid >> 5;
    int lane = tid & 31;
    int i = blockIdx.x * blockDim.x + tid;
    bool valid = (i < N_NODES);
    unsigned k = valid ? g_keys[i] : 0u;
    unsigned p = k >> 16;
    unsigned P = g_P16;
    bool sel = valid && (p > P);
    bool eq = valid && (p == P);
    if (valid) g_flag[i] = sel ? 1 : 0;

    unsigned mSel = __ballot_sync(0xFFFFFFFFu, sel);
    unsigned mEq = __ballot_sync(0xFFFFFFFFu, eq);
    if (lane == 0) { s_wsel[wid] = __popc(mSel); s_weq[wid] = __popc(mEq); }
    __syncthreads();
    if (tid == 0) {
        int accS = 0, accE = 0;
#pragma unroll
        for (int wdx = 0; wdx < 8; wdx++) {
            s_osel[wdx] = accS; accS += s_wsel[wdx];
            s_oeq[wdx] = accE; accE += s_weq[wdx];
        }
        s_bsel = accS ? atomicAdd(&g_counters[C_SEL], accS) : 0;
        s_beq = accE ? atomicAdd(&g_counters[C_EQ], accE) : 0;
    }
    __syncthreads();
    unsigned lt = (1u << lane) - 1u;
    if (sel) {
        int pos = s_bsel + s_osel[wid] + __popc(mSel & lt);
        if (pos < S_SAMPLE + M_TILE) g_sel[pos] = i;
    }
    if (eq) {
        int pos = s_beq + s_oeq[wid] + __popc(mEq & lt);
        if (pos < EQCAP) g_eqPair[pos] = make_uint2(k, (unsigned)i);
    }
}

// ---------------------------------------------------------------------------
// eq_resolve: O(n) in-bin radix descent over (key, idx) pairs — linear reads.
// ---------------------------------------------------------------------------
__global__ void eq_resolve_kernel() {
    __shared__ unsigned hist[256];
    __shared__ unsigned suf[256];
    __shared__ unsigned sb, sneed;
    __shared__ int tie_idx[64];
    __shared__ unsigned tie_cnt;
    int t = threadIdx.x;
    int n = g_counters[C_EQ];
    if (n > EQCAP) n = EQCAP;
    unsigned d = (unsigned)g_counters[C_REM];

    // level 2: bits [15:8]
    hist[t] = 0;
    if (t == 0) tie_cnt = 0;
    __syncthreads();
    for (int j = t; j < n; j += 256)
        atomicAdd(&hist[(g_eqPair[j].x >> 8) & 255u], 1u);
    __syncthreads();
    pick256(hist, d, &sb, &sneed, suf);
    __syncthreads();
    unsigned b2 = sb, need3 = sneed;

    // level 3: bits [7:0] among keys with bits[15:8]==b2
    hist[t] = 0;
    __syncthreads();
    for (int j = t; j < n; j += 256) {
        unsigned k = g_eqPair[j].x;
        if (((k >> 8) & 255u) == b2) atomicAdd(&hist[k & 255u], 1u);
    }
    __syncthreads();
    pick256(hist, need3, &sb, &sneed, suf);
    __syncthreads();
    unsigned T32 = (g_P16 << 16) | (b2 << 8) | sb;
    unsigned ties_needed = sneed;

    // selection pass (linear)
    for (int j = t; j < n; j += 256) {
        uint2 pr = g_eqPair[j];
        if (pr.x > T32) {
            g_flag[pr.y] = 1;
            int q = atomicAdd(&g_counters[C_SEL], 1);
            if (q < S_SAMPLE + M_TILE) g_sel[q] = (int)pr.y;
        } else if (pr.x == T32) {
            unsigned e = atomicAdd(&tie_cnt, 1u);
            if (e < 64) tie_idx[e] = (int)pr.y;
        }
    }
    __syncthreads();
    int m = (tie_cnt < 64u) ? (int)tie_cnt : 64;
    if (t < m) {
        int idx = tie_idx[t];
        int rank = 0;
        for (int j = 0; j < m; j++) rank += (tie_idx[j] < idx) ? 1 : 0;
        if (rank < (int)ties_needed) {
            g_flag[idx] = 1;
            int q = atomicAdd(&g_counters[C_SEL], 1);
            if (q < S_SAMPLE + M_TILE) g_sel[q] = idx;
        }
    }
}

// ---------------------------------------------------------------------------
// zero: unselected rows (no smem -> full occupancy, pure BW)
// ---------------------------------------------------------------------------
__global__ void zero_kernel(float* __restrict__ out) {
    int gw = (blockIdx.x * blockDim.x + threadIdx.x) >> 5;
    int lane = threadIdx.x & 31;
    int nw = (gridDim.x * blockDim.x) >> 5;
    float4 z = make_float4(0.f, 0.f, 0.f, 0.f);
    for (int row = gw; row < N_NODES; row += nw) {
        if (!g_flag[row]) {
            float4* p = (float4*)(out + (size_t)row * OUT_C);
            p[lane] = z;
            p[lane + 32] = z;
        }
    }
}

// ---------------------------------------------------------------------------
// HMMA GEMM — byte-for-byte the round-6 version (measured inside 219us):
// M=64 gathered rows x N=256, K=256 in 32-chunks; 8 warps x (2x8) m16n8k16.
// ---------------------------------------------------------------------------
#define A_STRIDE 40    // halves; 80B rows -> bank step 20, conflict-free
#define B_STRIDE 264   // halves; 528B rows -> bank step 4, conflict-free

__device__ __forceinline__ uint32_t smem_u32(const void* p) {
    uint32_t a;
    asm("{ .reg .u64 t; cvta.to.shared.u64 t, %1; cvt.u32.u64 %0, t; }"
        : "=r"(a) : "l"(p));
    return a;
}

__global__ void __launch_bounds__(256, 2) gemm_kernel(
    const float* __restrict__ x, const float* __restrict__ bias,
    float* __restrict__ out) {
    __shared__ __align__(16) __half As[M_TILE * A_STRIDE];   // 5120 B
    __shared__ __align__(16) __half Bs[32 * B_STRIDE];       // 16896 B
    __shared__ int rows_s[M_TILE];

    int tid = threadIdx.x;
    int wid = tid >> 5;
    int lane = tid & 31;
    int r0 = blockIdx.x * M_TILE;

    if (tid < M_TILE) {
        int rr = r0 + tid;
        rows_s[tid] = g_sel[(rr < S_SAMPLE) ? rr : r0];
    }
    __syncthreads();

    int m_half = wid & 1;
    int n_quad = wid >> 1;

    float acc[2][8][4];
#pragma unroll
    for (int mt = 0; mt < 2; mt++)
#pragma unroll
        for (int nt = 0; nt < 8; nt++)
#pragma unroll
            for (int q = 0; q < 4; q++) acc[mt][nt][q] = 0.f;

    int a_row = tid >> 2;
    int a_part = (tid & 3) * 8;
    int b_krow = tid >> 3;
    int b_seg = (tid & 7) * 32;

    const uint32_t As_base = smem_u32(As);
    const uint32_t Bs_base = smem_u32(Bs);

    for (int k0 = 0; k0 < IN_C; k0 += 32) {
        if (k0) __syncthreads();
        {
            const float4* src =
                (const float4*)(x + (size_t)rows_s[a_row] * IN_C + k0 + a_part);
            float4 v0 = src[0];
            float4 v1 = src[1];
            __half2 h0 = __floats2half2_rn(v0.x, v0.y);
            __half2 h1 = __floats2half2_rn(v0.z, v0.w);
            __half2 h2 = __floats2half2_rn(v1.x, v1.y);
            __half2 h3 = __floats2half2_rn(v1.z, v1.w);
            unsigned* dst = (unsigned*)&As[a_row * A_STRIDE + a_part];
            dst[0] = *(unsigned*)&h0;
            dst[1] = *(unsigned*)&h1;
            dst[2] = *(unsigned*)&h2;
            dst[3] = *(unsigned*)&h3;
        }
        {
            const uint4* src = (const uint4*)&g_wh[(k0 + b_krow) * 128 + b_seg / 2];
            uint4* dst = (uint4*)&Bs[b_krow * B_STRIDE + b_seg];
            dst[0] = src[0];
            dst[1] = src[1];
            dst[2] = src[2];
            dst[3] = src[3];
        }
        __syncthreads();

#pragma unroll
        for (int ks = 0; ks < 2; ks++) {
            uint32_t af[2][4];
#pragma unroll
            for (int mt = 0; mt < 2; mt++) {
                int row = m_half * 32 + mt * 16 + (lane & 15);
                int col = ks * 16 + (lane >> 4) * 8;
                uint32_t addr = As_base + (row * A_STRIDE + col) * 2;
                asm volatile(
                    "ldmatrix.sync.aligned.m8n8.x4.shared.b16 {%0,%1,%2,%3}, [%4];"
                    : "=r"(af[mt][0]), "=r"(af[mt][1]),
                      "=r"(af[mt][2]), "=r"(af[mt][3]) : "r"(addr));
            }
            uint32_t bf[8][2];
#pragma unroll
            for (int nt = 0; nt < 8; nt++) {
                int krow = ks * 16 + (lane & 15);
                int ncol = n_quad * 64 + nt * 8;
                uint32_t addr = Bs_base + (krow * B_STRIDE + ncol) * 2;
                asm volatile(
                    "ldmatrix.sync.aligned.m8n8.x2.trans.shared.b16 {%0,%1}, [%2];"
                    : "=r"(bf[nt][0]), "=r"(bf[nt][1]) : "r"(addr));
            }
#pragma unroll
            for (int mt = 0; mt < 2; mt++)
#pragma unroll
                for (int nt = 0; nt < 8; nt++) {
                    asm volatile(
                        "mma.sync.aligned.m16n8k16.row.col.f32.f16.f16.f32 "
                        "{%0,%1,%2,%3}, {%4,%5,%6,%7}, {%8,%9}, {%0,%1,%2,%3};"
                        : "+f"(acc[mt][nt][0]), "+f"(acc[mt][nt][1]),
                          "+f"(acc[mt][nt][2]), "+f"(acc[mt][nt][3])
                        : "r"(af[mt][0]), "r"(af[mt][1]),
                          "r"(af[mt][2]), "r"(af[mt][3]),
                          "r"(bf[nt][0]), "r"(bf[nt][1]));
                }
        }
    }

    const float scale = 5.0f;
    int qr = lane >> 2;
    int qc = (lane & 3) * 2;
#pragma unroll
    for (int mt = 0; mt < 2; mt++) {
        int lrow_lo = m_half * 32 + mt * 16 + qr;
        int g_lo = rows_s[lrow_lo];
        int g_hi = rows_s[lrow_lo + 8];
        float* row_lo = out + (size_t)g_lo * OUT_C;
        float* row_hi = out + (size_t)g_hi * OUT_C;
#pragma unroll
        for (int nt = 0; nt < 8; nt++) {
            int col = n_quad * 64 + nt * 8 + qc;
            float b0 = bias[col], b1 = bias[col + 1];
            *(float2*)(row_lo + col) = make_float2(
                (acc[mt][nt][0] + b0) * scale, (acc[mt][nt][1] + b1) * scale);
            *(float2*)(row_hi + col) = make_float2(
                (acc[mt][nt][2] + b0) * scale, (acc[mt][nt][3] + b1) * scale);
        }
    }
}

// ---------------------------------------------------------------------------
// Launch
// ---------------------------------------------------------------------------
extern "C" void kernel_launch(void* const* d_in, const int* in_sizes, int n_in,
                              void* d_out, int out_size) {
    const float* x = nullptr;
    const float* w = nullptr;
    const float* bias = nullptr;
    const float* imp = nullptr;
    for (int i = 0; i < n_in; i++) {
        switch (in_sizes[i]) {
            case 128000000: x = (const float*)d_in[i]; break;
            case 65536:     w = (const float*)d_in[i]; break;
            case 256:       bias = (const float*)d_in[i]; break;
            case 500000:    imp = (const float*)d_in[i]; break;
            default: break;  // edge_index unused
        }
    }
    float* out = (float*)d_out;
    (void)out_size;

    prep_kernel<<<128, 256>>>(w);
    score_kernel<<<(N_NODES + 255) / 256, 256>>>(imp);
    hist2_kernel<<<512, 256>>>();
    flag_kernel<<<(N_NODES + 255) / 256, 256>>>();
    eq_resolve_kernel<<<1, 256>>>();
    zero_kernel<<<1024, 256>>>(out);
    gemm_kernel<<<NBLK, 256>>>(x, bias, out);
}

// round 11
// speedup vs baseline: 49.5276x; 1.0461x over previous
#include <cuda_runtime.h>
#include <cuda_fp16.h>
#include <cstdint>

// ---------------------------------------------------------------------------
// Problem constants
// ---------------------------------------------------------------------------
#define N_NODES 500000
#define S_SAMPLE 100000
#define EQCAP 32768
#define OUT_C 256
#define IN_C 256
#define M_TILE 64
#define NBLK ((S_SAMPLE + M_TILE - 1) / M_TILE)   // 1563

// libdevice accurate log (immune to fast-math logf substitution)
extern "C" __device__ float __nv_logf(float);

// ---------------------------------------------------------------------------
// Device scratch
// ---------------------------------------------------------------------------
__device__ unsigned g_keys[N_NODES];
__device__ unsigned char g_flag[N_NODES];   // only eq rows use this
__device__ int g_sel[S_SAMPLE + M_TILE];
__device__ uint2 g_eqPair[EQCAP];           // (key, idx)
__device__ unsigned g_c256[256];
__device__ unsigned g_m256[256];
__device__ unsigned g_B0;
__device__ unsigned g_P16;
__device__ int g_counters[4];
__device__ unsigned g_done[2];
__device__ volatile unsigned g_eqDone;
__device__ unsigned g_wh[32768];            // w as f16 pairs, [k][n]
#define C_SEL 0
#define C_EQ 1
#define C_REM 2

// ---------------------------------------------------------------------------
// Threefry-2x32, partitionable: x0=0, x1=i, key=(0,42); draw = out0 ^ out1
// ---------------------------------------------------------------------------
__device__ __forceinline__ unsigned rotl32(unsigned x, int r) {
    return (x << r) | (x >> (32 - r));
}
__device__ __forceinline__ unsigned threefry_bits(unsigned i) {
    const unsigned ks0 = 0u, ks1 = 42u;
    const unsigned ks2 = 0x1BD11BDAu ^ ks0 ^ ks1;
    unsigned x0 = 0u + ks0;
    unsigned x1 = i + ks1;
#define TF_R4(a, b, c, d)                                   \
    x0 += x1; x1 = rotl32(x1, a); x1 ^= x0;                 \
    x0 += x1; x1 = rotl32(x1, b); x1 ^= x0;                 \
    x0 += x1; x1 = rotl32(x1, c); x1 ^= x0;                 \
    x0 += x1; x1 = rotl32(x1, d); x1 ^= x0;
    TF_R4(13, 15, 26, 6)  x0 += ks1; x1 += ks2 + 1u;
    TF_R4(17, 29, 16, 24) x0 += ks2; x1 += ks0 + 2u;
    TF_R4(13, 15, 26, 6)  x0 += ks0; x1 += ks1 + 3u;
    TF_R4(17, 29, 16, 24) x0 += ks1; x1 += ks2 + 4u;
    TF_R4(13, 15, 26, 6)  x0 += ks2; x1 += ks0 + 5u;
#undef TF_R4
    return x0 ^ x1;
}
__device__ __forceinline__ unsigned f2key(float f) {
    unsigned b = __float_as_uint(f);
    return (b & 0x80000000u) ? ~b : (b | 0x80000000u);
}

// ---------------------------------------------------------------------------
// suffix-scan pick over a 256-bin hist (in-block)
// ---------------------------------------------------------------------------
__device__ void pick256(const unsigned* hist, unsigned need,
                        unsigned* out_bin, unsigned* out_rem, unsigned* suf) {
    int t = threadIdx.x;
    suf[t] = hist[t];
    __syncthreads();
#pragma unroll
    for (int off = 1; off < 256; off <<= 1) {
        unsigned v = (t + off < 256) ? suf[t + off] : 0u;
        __syncthreads();
        suf[t] += v;
        __syncthreads();
    }
    unsigned above = (t < 255) ? suf[t + 1] : 0u;
    if (suf[t] >= need && above < need) {
        *out_bin = (unsigned)t;
        *out_rem = need - above;
        __threadfence();
    }
    __syncthreads();
}

// ---------------------------------------------------------------------------
// prep: zero counters + convert w to f16
// ---------------------------------------------------------------------------
__global__ void prep_kernel(const float* __restrict__ w) {
    int t = blockIdx.x * blockDim.x + threadIdx.x;   // 32768 threads
    if (t < 256) { g_c256[t] = 0; g_m256[t] = 0; }
    if (t < 4) g_counters[t] = 0;
    if (t < 2) g_done[t] = 0;
    if (t == 0) g_eqDone = 0;
    float2 v = ((const float2*)w)[t];
    __half2 h = __floats2half2_rn(v.x, v.y);
    g_wh[t] = *(unsigned*)&h;
}

// ---------------------------------------------------------------------------
// score: keys + shared coarse hist (bits[31:24]) + fused pick8 in tail block
// ---------------------------------------------------------------------------
__global__ void score_kernel(const float* __restrict__ imp) {
    __shared__ unsigned sh[256];
    __shared__ unsigned is_last;
    int tid = threadIdx.x;
    sh[tid] = 0;
    if (tid == 0) is_last = 0;
    __syncthreads();
    int i = blockIdx.x * blockDim.x + tid;
    if (i < N_NODES) {
        unsigned bits = threefry_bits((unsigned)i);
        float f = __uint_as_float((bits >> 9) | 0x3F800000u) - 1.0f;
        float u = f + 1.17549435e-38f;
        float g = -__nv_logf(-__nv_logf(u));
        unsigned k = f2key(__nv_logf(imp[i]) + g);
        g_keys[i] = k;
        atomicAdd(&sh[k >> 24], 1u);
    }
    __syncthreads();
    if (sh[tid]) atomicAdd(&g_c256[tid], sh[tid]);
    __threadfence();
    __syncthreads();
    if (tid == 0) {
        unsigned old = atomicAdd(&g_done[0], 1u);
        if (old == gridDim.x - 1) is_last = 1;
    }
    __syncthreads();
    if (is_last)
        pick256(g_c256, S_SAMPLE, &g_B0, (unsigned*)&g_counters[C_REM], sh);
}

// ---------------------------------------------------------------------------
// hist2: bits[23:16] hist among keys with top byte == B0 (+ fused pick16)
// ---------------------------------------------------------------------------
__global__ void hist2_kernel() {
    __shared__ unsigned sh[256];
    __shared__ unsigned is_last;
    int tid = threadIdx.x;
    sh[tid] = 0;
    if (tid == 0) is_last = 0;
    __syncthreads();
    unsigned b0 = g_B0;
    int stride = gridDim.x * blockDim.x;
    for (int i = blockIdx.x * blockDim.x + tid; i < N_NODES; i += stride) {
        unsigned k = g_keys[i];
        if ((k >> 24) == b0) atomicAdd(&sh[(k >> 16) & 255u], 1u);
    }
    __syncthreads();
    if (sh[tid]) atomicAdd(&g_m256[tid], sh[tid]);
    __threadfence();
    __syncthreads();
    if (tid == 0) {
        unsigned old = atomicAdd(&g_done[1], 1u);
        if (old == gridDim.x - 1) is_last = 1;
    }
    __syncthreads();
    if (is_last) {
        __shared__ unsigned sbin, srem;
        pick256(g_m256, (unsigned)g_counters[C_REM], &sbin, &srem, sh);
        if (tid == 0) {
            g_P16 = (g_B0 << 8) | sbin;
            g_counters[C_REM] = (int)srem;
        }
    }
}

// ---------------------------------------------------------------------------
// flagzero: classify + compact sel/eq lists + zero definite-loser rows inline
// ---------------------------------------------------------------------------
__global__ void flagzero_kernel(float* __restrict__ out) {
    __shared__ int s_wsel[8], s_weq[8];
    __shared__ int s_osel[8], s_oeq[8];
    __shared__ int s_bsel, s_beq;
    int tid = threadIdx.x;
    int wid = tid >> 5;
    int lane = tid & 31;
    int i = blockIdx.x * blockDim.x + tid;
    bool valid = (i < N_NODES);
    unsigned k = valid ? g_keys[i] : 0u;
    unsigned p = k >> 16;
    unsigned P = g_P16;
    bool sel = valid && (p > P);
    bool eq = valid && (p == P);
    if (eq) g_flag[i] = 0;   // eq rows start unselected; eq block sets winners

    unsigned mSel = __ballot_sync(0xFFFFFFFFu, sel);
    unsigned mEq = __ballot_sync(0xFFFFFFFFu, eq);
    if (lane == 0) { s_wsel[wid] = __popc(mSel); s_weq[wid] = __popc(mEq); }
    __syncthreads();
    if (tid == 0) {
        int accS = 0, accE = 0;
#pragma unroll
        for (int wdx = 0; wdx < 8; wdx++) {
            s_osel[wdx] = accS; accS += s_wsel[wdx];
            s_oeq[wdx] = accE; accE += s_weq[wdx];
        }
        s_bsel = accS ? atomicAdd(&g_counters[C_SEL], accS) : 0;
        s_beq = accE ? atomicAdd(&g_counters[C_EQ], accE) : 0;
    }
    __syncthreads();
    unsigned lt = (1u << lane) - 1u;
    if (sel) {
        int pos = s_bsel + s_osel[wid] + __popc(mSel & lt);
        if (pos < S_SAMPLE + M_TILE) g_sel[pos] = i;
    }
    if (eq) {
        int pos = s_beq + s_oeq[wid] + __popc(mEq & lt);
        if (pos < EQCAP) g_eqPair[pos] = make_uint2(k, (unsigned)i);
    }

    // zero definite losers (warp-cooperative, one row per iteration)
    unsigned mZero = __ballot_sync(0xFFFFFFFFu, valid && !sel && !eq);
    int rowbase = blockIdx.x * 256 + wid * 32;
    float4 z = make_float4(0.f, 0.f, 0.f, 0.f);
    for (unsigned m = mZero; m; m &= (m - 1)) {
        int r = __ffs(m) - 1;
        float4* pr = (float4*)(out + (size_t)(rowbase + r) * OUT_C);
        pr[lane] = z;
        pr[lane + 32] = z;
    }
}

// ---------------------------------------------------------------------------
// eq_combined: block 0 radix-resolves exact T32 + winner selection;
// all 64 blocks then zero eq-loser rows (block 1..63 spin on done flag).
// ---------------------------------------------------------------------------
__global__ void eq_combined_kernel(float* __restrict__ out) {
    __shared__ unsigned hist[256];
    __shared__ unsigned suf[256];
    __shared__ unsigned sb, sneed;
    __shared__ int tie_idx[64];
    __shared__ unsigned tie_cnt;
    int t = threadIdx.x;
    int n = g_counters[C_EQ];
    if (n > EQCAP) n = EQCAP;

    if (blockIdx.x == 0) {
        unsigned d = (unsigned)g_counters[C_REM];
        // level 2: bits [15:8]
        hist[t] = 0;
        if (t == 0) tie_cnt = 0;
        __syncthreads();
        for (int j = t; j < n; j += 256)
            atomicAdd(&hist[(g_eqPair[j].x >> 8) & 255u], 1u);
        __syncthreads();
        pick256(hist, d, &sb, &sneed, suf);
        __syncthreads();
        unsigned b2 = sb, need3 = sneed;
        // level 3: bits [7:0]
        hist[t] = 0;
        __syncthreads();
        for (int j = t; j < n; j += 256) {
            unsigned k = g_eqPair[j].x;
            if (((k >> 8) & 255u) == b2) atomicAdd(&hist[k & 255u], 1u);
        }
        __syncthreads();
        pick256(hist, need3, &sb, &sneed, suf);
        __syncthreads();
        unsigned T32 = (g_P16 << 16) | (b2 << 8) | sb;
        unsigned ties_needed = sneed;

        for (int j = t; j < n; j += 256) {
            uint2 pr = g_eqPair[j];
            if (pr.x > T32) {
                g_flag[pr.y] = 1;
                int q = atomicAdd(&g_counters[C_SEL], 1);
                if (q < S_SAMPLE + M_TILE) g_sel[q] = (int)pr.y;
            } else if (pr.x == T32) {
                unsigned e = atomicAdd(&tie_cnt, 1u);
                if (e < 64) tie_idx[e] = (int)pr.y;
            }
        }
        __syncthreads();
        int m = (tie_cnt < 64u) ? (int)tie_cnt : 64;
        if (t < m) {
            int idx = tie_idx[t];
            int rank = 0;
            for (int j = 0; j < m; j++) rank += (tie_idx[j] < idx) ? 1 : 0;
            if (rank < (int)ties_needed) {
                g_flag[idx] = 1;
                int q = atomicAdd(&g_counters[C_SEL], 1);
                if (q < S_SAMPLE + M_TILE) g_sel[q] = idx;
            }
        }
        __threadfence();
        __syncthreads();
        if (t == 0) g_eqDone = 1;
        __syncthreads();
    } else {
        if (t == 0) {
            while (g_eqDone == 0) { __nanosleep(64); }
        }
        __syncthreads();
    }

    // all 64 blocks: zero eq losers (flag still 0)
    int lane = t & 31;
    int gw = blockIdx.x * 8 + (t >> 5);   // 512 warps
    float4 z = make_float4(0.f, 0.f, 0.f, 0.f);
    for (int base = gw * 32; base < n; base += 512 * 32) {
        int j = base + lane;
        int idx = -1;
        bool loser = false;
        if (j < n) {
            idx = (int)g_eqPair[j].y;
            loser = (g_flag[idx] == 0);
        }
        unsigned m = __ballot_sync(0xFFFFFFFFu, loser);
        while (m) {
            int r = __ffs(m) - 1;
            m &= (m - 1);
            int row = __shfl_sync(0xFFFFFFFFu, idx, r);
            float4* pr = (float4*)(out + (size_t)row * OUT_C);
            pr[lane] = z;
            pr[lane + 32] = z;
        }
    }
}

// ---------------------------------------------------------------------------
// HMMA GEMM — round-6 kernel + register prefetch software pipeline.
// M=64 gathered rows x N=256, K=256 in 32-chunks; 8 warps x (2x8) m16n8k16.
// ---------------------------------------------------------------------------
#define A_STRIDE 40    // halves; conflict-free
#define B_STRIDE 264   // halves; conflict-free

__device__ __forceinline__ uint32_t smem_u32(const void* p) {
    uint32_t a;
    asm("{ .reg .u64 t; cvta.to.shared.u64 t, %1; cvt.u32.u64 %0, t; }"
        : "=r"(a) : "l"(p));
    return a;
}

__global__ void __launch_bounds__(256) gemm_kernel(
    const float* __restrict__ x, const float* __restrict__ bias,
    float* __restrict__ out) {
    __shared__ __align__(16) __half As[M_TILE * A_STRIDE];
    __shared__ __align__(16) __half Bs[32 * B_STRIDE];
    __shared__ int rows_s[M_TILE];

    int tid = threadIdx.x;
    int wid = tid >> 5;
    int lane = tid & 31;
    int r0 = blockIdx.x * M_TILE;

    if (tid < M_TILE) {
        int rr = r0 + tid;
        rows_s[tid] = g_sel[(rr < S_SAMPLE) ? rr : r0];
    }
    __syncthreads();

    int m_half = wid & 1;
    int n_quad = wid >> 1;

    float acc[2][8][4];
#pragma unroll
    for (int mt = 0; mt < 2; mt++)
#pragma unroll
        for (int nt = 0; nt < 8; nt++)
#pragma unroll
            for (int q = 0; q < 4; q++) acc[mt][nt][q] = 0.f;

    int a_row = tid >> 2;
    int a_part = (tid & 3) * 8;
    int b_krow = tid >> 3;
    int b_seg = (tid & 7) * 32;

    const uint32_t As_base = smem_u32(As);
    const uint32_t Bs_base = smem_u32(Bs);
    const float4* a_src = (const float4*)(x + (size_t)rows_s[a_row] * IN_C + a_part);

    // prefetch chunk 0
    float4 pa0 = a_src[0];
    float4 pa1 = a_src[1];
    const uint4* b_src0 = (const uint4*)&g_wh[b_krow * 128 + b_seg / 2];
    uint4 pb0 = b_src0[0], pb1 = b_src0[1], pb2 = b_src0[2], pb3 = b_src0[3];

    for (int kc = 0; kc < 8; kc++) {
        // store prefetched chunk kc
        {
            __half2 h0 = __floats2half2_rn(pa0.x, pa0.y);
            __half2 h1 = __floats2half2_rn(pa0.z, pa0.w);
            __half2 h2 = __floats2half2_rn(pa1.x, pa1.y);
            __half2 h3 = __floats2half2_rn(pa1.z, pa1.w);
            unsigned* dst = (unsigned*)&As[a_row * A_STRIDE + a_part];
            dst[0] = *(unsigned*)&h0;
            dst[1] = *(unsigned*)&h1;
            dst[2] = *(unsigned*)&h2;
            dst[3] = *(unsigned*)&h3;
            uint4* bdst = (uint4*)&Bs[b_krow * B_STRIDE + b_seg];
            bdst[0] = pb0; bdst[1] = pb1; bdst[2] = pb2; bdst[3] = pb3;
        }
        __syncthreads();

        // issue loads for chunk kc+1 (hidden under MMA below)
        if (kc < 7) {
            int k0n = (kc + 1) * 32;
            const float4* an = (const float4*)((const float*)a_src + k0n);
            pa0 = an[0];
            pa1 = an[1];
            const uint4* bn = (const uint4*)&g_wh[(k0n + b_krow) * 128 + b_seg / 2];
            pb0 = bn[0]; pb1 = bn[1]; pb2 = bn[2]; pb3 = bn[3];
        }

#pragma unroll
        for (int ks = 0; ks < 2; ks++) {
            uint32_t af[2][4];
#pragma unroll
            for (int mt = 0; mt < 2; mt++) {
                int row = m_half * 32 + mt * 16 + (lane & 15);
                int col = ks * 16 + (lane >> 4) * 8;
                uint32_t addr = As_base + (row * A_STRIDE + col) * 2;
                asm volatile(
                    "ldmatrix.sync.aligned.m8n8.x4.shared.b16 {%0,%1,%2,%3}, [%4];"
                    : "=r"(af[mt][0]), "=r"(af[mt][1]),
                      "=r"(af[mt][2]), "=r"(af[mt][3]) : "r"(addr));
            }
            uint32_t bf[8][2];
#pragma unroll
            for (int nt = 0; nt < 8; nt++) {
                int krow = ks * 16 + (lane & 15);
                int ncol = n_quad * 64 + nt * 8;
                uint32_t addr = Bs_base + (krow * B_STRIDE + ncol) * 2;
                asm volatile(
                    "ldmatrix.sync.aligned.m8n8.x2.trans.shared.b16 {%0,%1}, [%2];"
                    : "=r"(bf[nt][0]), "=r"(bf[nt][1]) : "r"(addr));
            }
#pragma unroll
            for (int mt = 0; mt < 2; mt++)
#pragma unroll
                for (int nt = 0; nt < 8; nt++) {
                    asm volatile(
                        "mma.sync.aligned.m16n8k16.row.col.f32.f16.f16.f32 "
                        "{%0,%1,%2,%3}, {%4,%5,%6,%7}, {%8,%9}, {%0,%1,%2,%3};"
                        : "+f"(acc[mt][nt][0]), "+f"(acc[mt][nt][1]),
                          "+f"(acc[mt][nt][2]), "+f"(acc[mt][nt][3])
                        : "r"(af[mt][0]), "r"(af[mt][1]),
                          "r"(af[mt][2]), "r"(af[mt][3]),
                          "r"(bf[nt][0]), "r"(bf[nt][1]));
                }
        }
        if (kc < 7) __syncthreads();   // smem consumed; next store may proceed
    }

    const float scale = 5.0f;
    int qr = lane >> 2;
    int qc = (lane & 3) * 2;
#pragma unroll
    for (int mt = 0; mt < 2; mt++) {
        int lrow_lo = m_half * 32 + mt * 16 + qr;
        int g_lo = rows_s[lrow_lo];
        int g_hi = rows_s[lrow_lo + 8];
        float* row_lo = out + (size_t)g_lo * OUT_C;
        float* row_hi = out + (size_t)g_hi * OUT_C;
#pragma unroll
        for (int nt = 0; nt < 8; nt++) {
            int col = n_quad * 64 + nt * 8 + qc;
            float b0 = bias[col], b1 = bias[col + 1];
            *(float2*)(row_lo + col) = make_float2(
                (acc[mt][nt][0] + b0) * scale, (acc[mt][nt][1] + b1) * scale);
            *(float2*)(row_hi + col) = make_float2(
                (acc[mt][nt][2] + b0) * scale, (acc[mt][nt][3] + b1) * scale);
        }
    }
}

// ---------------------------------------------------------------------------
// Launch
// ---------------------------------------------------------------------------
extern "C" void kernel_launch(void* const* d_in, const int* in_sizes, int n_in,
                              void* d_out, int out_size) {
    const float* x = nullptr;
    const float* w = nullptr;
    const float* bias = nullptr;
    const float* imp = nullptr;
    for (int i = 0; i < n_in; i++) {
        switch (in_sizes[i]) {
            case 128000000: x = (const float*)d_in[i]; break;
            case 65536:     w = (const float*)d_in[i]; break;
            case 256:       bias = (const float*)d_in[i]; break;
            case 500000:    imp = (const float*)d_in[i]; break;
            default: break;  // edge_index unused
        }
    }
    float* out = (float*)d_out;
    (void)out_size;

    prep_kernel<<<128, 256>>>(w);
    score_kernel<<<(N_NODES + 255) / 256, 256>>>(imp);
    hist2_kernel<<<512, 256>>>();
    flagzero_kernel<<<(N_NODES + 255) / 256, 256>>>(out);
    eq_combined_kernel<<<64, 256>>>(out);
    gemm_kernel<<<NBLK, 256>>>(x, bias, out);
}